// round 3
// baseline (speedup 1.0000x reference)
#include <cuda_runtime.h>
#include <cmath>

#define NUM_S 7
#define NUM_R 6
#define MAX_EDGES 200000
#define RBF_STRIDE 56   // 7 l-groups padded to 8 floats each

// Per-edge precomputed radial basis, padded layout [e][l][8] (j=0..5 valid).
__device__ float g_rbf[(size_t)MAX_EDGES * RBF_STRIDE];

// l index for each of the 49 sph-harm columns (l repeated 2l+1 times)
__constant__ int c_LIDX[49] = {
    0,
    1,1,1,
    2,2,2,2,2,
    3,3,3,3,3,3,3,
    4,4,4,4,4,4,4,4,4,
    5,5,5,5,5,5,5,5,5,5,5,
    6,6,6,6,6,6,6,6,6,6,6,6,6
};

struct K1Params { float Z[NUM_S][NUM_R]; float C[NUM_S][NUM_R]; };  // C = BNORM * cutoff^-1.5
struct K2Params { float CK[NUM_S][NUM_S]; };                        // K(l,m) (* sqrt2 for m>0)

// ---------------- host-side constant computation (pure CPU, double) ----------------
static double sph_jn_d(int n, double x) {
    double j0 = sin(x) / x;
    if (n == 0) return j0;
    double j1 = sin(x) / (x * x) - cos(x) / x;
    double jm1 = j0, jc = j1;
    for (int l = 1; l < n; l++) {
        double t = (2.0 * l + 1.0) / x * jc - jm1;
        jm1 = jc; jc = t;
    }
    return jc;
}

struct HostConsts { K1Params p1; K2Params p2; };

static HostConsts compute_consts() {
    const double PI = 3.14159265358979323846;
    double Z[NUM_S][NUM_R];
    double points[NUM_S + NUM_R];
    for (int k = 0; k < NUM_R; k++) Z[0][k] = (k + 1) * PI;
    int npts = NUM_R + NUM_S - 1;                 // 12
    for (int i = 0; i < npts; i++) points[i] = (i + 1) * PI;
    double racines[NUM_S + NUM_R];
    for (int order = 1; order < NUM_S; order++) {
        int nroots = NUM_R + NUM_S - 1 - order;
        for (int j = 0; j < nroots; j++) {
            double a = points[j], b = points[j + 1];
            double fa = sph_jn_d(order, a);
            for (int it = 0; it < 80; it++) {
                double m = 0.5 * (a + b);
                double fm = sph_jn_d(order, m);
                if (fa * fm <= 0.0) b = m; else { a = m; fa = fm; }
            }
            racines[j] = 0.5 * (a + b);
        }
        for (int i = 0; i < nroots; i++) points[i] = racines[i];
        for (int k = 0; k < NUM_R; k++) Z[order][k] = racines[k];
    }
    HostConsts h;
    double norm_const = pow(1.0 / 5.0, 1.5);
    for (int l = 0; l < NUM_S; l++)
        for (int j = 0; j < NUM_R; j++) {
            double bn = 1.0 / sqrt(0.5 * sph_jn_d(l + 1, Z[l][j]) * sph_jn_d(l + 1, Z[l][j]));
            h.p1.Z[l][j] = (float)Z[l][j];
            h.p1.C[l][j] = (float)(bn * norm_const);
        }
    double fact[16]; fact[0] = 1.0;
    for (int i = 1; i < 16; i++) fact[i] = fact[i - 1] * i;
    for (int l = 0; l < NUM_S; l++)
        for (int m = 0; m <= l; m++) {
            double K = sqrt((2.0 * l + 1.0) / (4.0 * PI) * fact[l - m] / fact[l + m]);
            if (m > 0) K *= sqrt(2.0);
            h.p2.CK[l][m] = (float)K;
        }
    return h;
}

static const HostConsts& host_consts() {
    static HostConsts h = compute_consts();   // CPU-only init; device work identical every call
    return h;
}

// ---------------- kernel 1: per-edge radial basis (42 values, padded to 56) ----------------
__global__ __launch_bounds__(256)
void k1_kernel(const float* __restrict__ D, int NE, K1Params P) {
    int e = blockIdx.x * blockDim.x + threadIdx.x;
    if (e >= NE) return;
    float d = D[e] * 0.2f;                    // D / CUTOFF
    float u;
    {
        float invd = 1.0f / d;
        float d2 = d * d, d4 = d2 * d2, d5 = d4 * d;
        u = invd + d5 * (-28.0f + d * (48.0f - 21.0f * d));
        if (!(d < 1.0f)) u = 0.0f;
    }
    float o[RBF_STRIDE];
#pragma unroll
    for (int l = 0; l < NUM_S; l++) {
#pragma unroll
        for (int j = 0; j < NUM_R; j++) {
            float x = d * P.Z[l][j];
            float s, c;
            sincosf(x, &s, &c);
            float invx = 1.0f / x;
            float cur = s * invx;             // j0
            if (l >= 1) {
                float prev = cur;
                cur = s * invx * invx - c * invx;   // j1 (same form as reference)
#pragma unroll
                for (int k = 1; k < l; k++) {
                    float nx = (2.0f * k + 1.0f) * invx * cur - prev;
                    prev = cur; cur = nx;
                }
            }
            o[l * 8 + j] = u * P.C[l][j] * cur;
        }
        o[l * 8 + 6] = 0.0f;
        o[l * 8 + 7] = 0.0f;
    }
    float4* dst = (float4*)(g_rbf + (size_t)e * RBF_STRIDE);
#pragma unroll
    for (int w = 0; w < 14; w++) dst[w] = ((float4*)o)[w];
}

// ---------------- kernel 2: sph harm + L2 gather + 470MB streaming write ----------------
#define QPB 128
// smem: sph [QPB][49] + edge idx [QPB]  -> 25.6 KB  => 8 CTAs/SM = 32 warps (50% occ)
#define K2_SMEM (QPB * 49 * 4 + QPB * 4)

__global__ __launch_bounds__(QPB, 8)
void k2_kernel(const float* __restrict__ Alpha, const float* __restrict__ Theta,
               const int* __restrict__ id4, float* __restrict__ out,
               int NQ, K2Params P) {
    extern __shared__ __align__(16) float smem[];
    float* sph_s = smem;                       // [QPB][49]
    int*   e_s   = (int*)(sph_s + QPB * 49);   // [QPB]

    int t = threadIdx.x;
    int q0 = blockIdx.x * QPB;
    int nq = min(QPB, NQ - q0);

    if (t < nq) e_s[t] = id4[q0 + t];

    // each thread computes the 49 sph-harm values for one quad
    if (t < nq) {
        float th = Alpha[q0 + t], ph = Theta[q0 + t];
        float st_, ct_;
        sincosf(th, &st_, &ct_);
        float* sp = sph_s + t * 49;
        float pmm = 1.0f;
#pragma unroll
        for (int m = 0; m < NUM_S; m++) {
            float cm, sm;
            if (m == 0) { cm = 1.0f; sm = 0.0f; }
            else sincosf((float)m * ph, &sm, &cm);
            float pa = pmm;
            {   // l = m
                int l = m;
                float k = P.CK[l][m];
                if (m == 0) sp[l * l] = k * pa;
                else { sp[l * l + m] = k * cm * pa; sp[(l + 1) * (l + 1) - m] = k * sm * pa; }
            }
            if (m < NUM_S - 1) {
                float pb = (2.0f * m + 1.0f) * ct_ * pa;
                {   // l = m+1
                    int l = m + 1;
                    float k = P.CK[l][m];
                    if (m == 0) sp[l * l] = k * pb;
                    else { sp[l * l + m] = k * cm * pb; sp[(l + 1) * (l + 1) - m] = k * sm * pb; }
                }
#pragma unroll
                for (int l = m + 2; l < NUM_S; l++) {
                    float pc = ((2.0f * l - 1.0f) * ct_ * pb - (float)(l + m - 1) * pa) / (float)(l - m);
                    pa = pb; pb = pc;
                    float k = P.CK[l][m];
                    if (m == 0) sp[l * l] = k * pc;
                    else { sp[l * l + m] = k * cm * pc; sp[(l + 1) * (l + 1) - m] = k * sm * pc; }
                }
            }
            pmm = (1.0f - 2.0f * (m + 1)) * st_ * pmm;
        }
    }
    __syncthreads();

    // phase B: 4 groups (96B, 16B-aligned) per iteration.
    // Explicit load-phase (8 independent LDGs -> MLP 8) then multiply-in-place,
    // then 6x STG.128 streaming.
    int total = nq * 49;
    int npack = total >> 2;
    for (int pi = t; pi < npack; pi += QPB) {
        int g0 = pi << 2;
        float4 ra[4]; float2 rb[4]; float s[4];
#pragma unroll
        for (int h = 0; h < 4; h++) {
            int g = g0 + h;
            int q = g / 49;
            int c = g - q * 49;
            int l = c_LIDX[c];
            s[h] = sph_s[q * 49 + c];
            const float* rp = g_rbf + (size_t)e_s[q] * RBF_STRIDE + l * 8;
            ra[h] = __ldg((const float4*)rp);
            rb[h] = __ldg((const float2*)(rp + 4));
        }
#pragma unroll
        for (int h = 0; h < 4; h++) {
            ra[h].x *= s[h]; ra[h].y *= s[h]; ra[h].z *= s[h]; ra[h].w *= s[h];
            rb[h].x *= s[h]; rb[h].y *= s[h];
        }
        float4* dst = (float4*)(out + ((size_t)q0 * 49 + (size_t)g0) * 6);
        __stcs(dst + 0, make_float4(ra[0].x, ra[0].y, ra[0].z, ra[0].w));
        __stcs(dst + 1, make_float4(rb[0].x, rb[0].y, ra[1].x, ra[1].y));
        __stcs(dst + 2, make_float4(ra[1].z, ra[1].w, rb[1].x, rb[1].y));
        __stcs(dst + 3, make_float4(ra[2].x, ra[2].y, ra[2].z, ra[2].w));
        __stcs(dst + 4, make_float4(rb[2].x, rb[2].y, ra[3].x, ra[3].y));
        __stcs(dst + 5, make_float4(ra[3].z, ra[3].w, rb[3].x, rb[3].y));
    }
    // tail (only in the last, partially-filled block): remaining <4 groups
    int rem = total & 3;
    if (t < rem) {
        int g = (npack << 2) + t;
        int q = g / 49, c = g - q * 49;
        int l = c_LIDX[c];
        float s = sph_s[q * 49 + c];
        const float* rp = g_rbf + (size_t)e_s[q] * RBF_STRIDE + l * 8;
        float4 r0 = __ldg((const float4*)rp);
        float2 r1 = __ldg((const float2*)(rp + 4));
        float2* dst = (float2*)(out + ((size_t)q0 * 49 + (size_t)g) * 6);
        __stcs(dst + 0, make_float2(s * r0.x, s * r0.y));
        __stcs(dst + 1, make_float2(s * r0.z, s * r0.w));
        __stcs(dst + 2, make_float2(s * r1.x, s * r1.y));
    }
}

extern "C" void kernel_launch(void* const* d_in, const int* in_sizes, int n_in,
                              void* d_out, int out_size) {
    const float* D   = (const float*)d_in[0];
    const float* Al  = (const float*)d_in[1];
    const float* Th  = (const float*)d_in[2];
    const int*   id4 = (const int*)d_in[3];
    float* out = (float*)d_out;
    int NE = in_sizes[0];
    int NQ = in_sizes[1];
    if (NE > MAX_EDGES) NE = MAX_EDGES;

    const HostConsts& H = host_consts();

    k1_kernel<<<(NE + 255) / 256, 256>>>(D, NE, H.p1);
    k2_kernel<<<(NQ + QPB - 1) / QPB, QPB, K2_SMEM>>>(Al, Th, id4, out, NQ, H.p2);
}

// round 5
// speedup vs baseline: 1.9415x; 1.9415x over previous
#include <cuda_runtime.h>
#include <cmath>

#define NUM_S 7
#define NUM_R 6
#define MAX_EDGES 200000
#define RBF_STRIDE 56   // g_rbf: 7 l-groups padded to 8 floats each (float4-friendly)

// Per-edge precomputed radial basis, padded layout [e][l][8] (j=0..5 valid).
__device__ float g_rbf[(size_t)MAX_EDGES * RBF_STRIDE];

struct K1Params { float Z[NUM_S][NUM_R]; float C[NUM_S][NUM_R]; };  // C = BNORM * cutoff^-1.5
struct K2Params { float CK[NUM_S][NUM_S]; };                        // K(l,m) (* sqrt2 for m>0)

// ---------------- host-side constant computation (pure CPU, double) ----------------
static double sph_jn_d(int n, double x) {
    double j0 = sin(x) / x;
    if (n == 0) return j0;
    double j1 = sin(x) / (x * x) - cos(x) / x;
    double jm1 = j0, jc = j1;
    for (int l = 1; l < n; l++) {
        double t = (2.0 * l + 1.0) / x * jc - jm1;
        jm1 = jc; jc = t;
    }
    return jc;
}

struct HostConsts { K1Params p1; K2Params p2; };

static HostConsts compute_consts() {
    const double PI = 3.14159265358979323846;
    double Z[NUM_S][NUM_R];
    double points[NUM_S + NUM_R];
    for (int k = 0; k < NUM_R; k++) Z[0][k] = (k + 1) * PI;
    int npts = NUM_R + NUM_S - 1;
    for (int i = 0; i < npts; i++) points[i] = (i + 1) * PI;
    double racines[NUM_S + NUM_R];
    for (int order = 1; order < NUM_S; order++) {
        int nroots = NUM_R + NUM_S - 1 - order;
        for (int j = 0; j < nroots; j++) {
            double a = points[j], b = points[j + 1];
            double fa = sph_jn_d(order, a);
            for (int it = 0; it < 80; it++) {
                double m = 0.5 * (a + b);
                double fm = sph_jn_d(order, m);
                if (fa * fm <= 0.0) b = m; else { a = m; fa = fm; }
            }
            racines[j] = 0.5 * (a + b);
        }
        for (int i = 0; i < nroots; i++) points[i] = racines[i];
        for (int k = 0; k < NUM_R; k++) Z[order][k] = racines[k];
    }
    HostConsts h;
    double norm_const = pow(1.0 / 5.0, 1.5);
    for (int l = 0; l < NUM_S; l++)
        for (int j = 0; j < NUM_R; j++) {
            double bn = 1.0 / sqrt(0.5 * sph_jn_d(l + 1, Z[l][j]) * sph_jn_d(l + 1, Z[l][j]));
            h.p1.Z[l][j] = (float)Z[l][j];
            h.p1.C[l][j] = (float)(bn * norm_const);
        }
    double fact[16]; fact[0] = 1.0;
    for (int i = 1; i < 16; i++) fact[i] = fact[i - 1] * i;
    for (int l = 0; l < NUM_S; l++)
        for (int m = 0; m <= l; m++) {
            double K = sqrt((2.0 * l + 1.0) / (4.0 * PI) * fact[l - m] / fact[l + m]);
            if (m > 0) K *= sqrt(2.0);
            h.p2.CK[l][m] = (float)K;
        }
    return h;
}

static const HostConsts& host_consts() {
    static HostConsts h = compute_consts();
    return h;
}

// ---------------- kernel 1: per-edge radial basis (42 values, padded to 56) ----------------
__global__ __launch_bounds__(256)
void k1_kernel(const float* __restrict__ D, int NE, K1Params P) {
    int e = blockIdx.x * blockDim.x + threadIdx.x;
    if (e >= NE) return;
    float d = D[e] * 0.2f;                    // D / CUTOFF
    float u;
    {
        float invd = 1.0f / d;
        float d2 = d * d, d4 = d2 * d2, d5 = d4 * d;
        u = invd + d5 * (-28.0f + d * (48.0f - 21.0f * d));
        if (!(d < 1.0f)) u = 0.0f;
    }
    float o[RBF_STRIDE];
#pragma unroll
    for (int l = 0; l < NUM_S; l++) {
#pragma unroll
        for (int j = 0; j < NUM_R; j++) {
            float x = d * P.Z[l][j];
            float s, c;
            sincosf(x, &s, &c);
            float invx = 1.0f / x;
            float cur = s * invx;             // j0
            if (l >= 1) {
                float prev = cur;
                cur = s * invx * invx - c * invx;   // j1 (same form as reference)
#pragma unroll
                for (int k = 1; k < l; k++) {
                    float nx = (2.0f * k + 1.0f) * invx * cur - prev;
                    prev = cur; cur = nx;
                }
            }
            o[l * 8 + j] = u * P.C[l][j] * cur;
        }
        o[l * 8 + 6] = 0.0f;
        o[l * 8 + 7] = 0.0f;
    }
    float4* dst = (float4*)(g_rbf + (size_t)e * RBF_STRIDE);
#pragma unroll
    for (int w = 0; w < 14; w++) dst[w] = ((float4*)o)[w];
}

// ---------------- kernel 2: sph + smem-staged rbf + fully coalesced stores ----------------
#define QPB 128
#define RBF_ROW 42                             // unpadded staged row: l*6+j
// smem: rbf [QPB][42] + sph [QPB][49] + tab[148] + e_s[QPB]
#define K2_SMEM (QPB * RBF_ROW * 4 + QPB * 49 * 4 + 148 * 4 + QPB * 4)

__global__ __launch_bounds__(QPB)
void k2_kernel(const float* __restrict__ Alpha, const float* __restrict__ Theta,
               const int* __restrict__ id4, float* __restrict__ out,
               int NQ, K2Params P) {
    extern __shared__ __align__(16) float smem[];
    float* rbf_s = smem;                           // [QPB][42]
    float* sph_s = rbf_s + QPB * RBF_ROW;          // [QPB][49]
    int*   tab_s = (int*)(sph_s + QPB * 49);       // [147] packed (c<<8)|wordoff
    int*   e_s   = tab_s + 148;                    // [QPB]

    int t = threadIdx.x;
    int q0 = blockIdx.x * QPB;
    int nq = min(QPB, NQ - q0);

    if (t < nq) e_s[t] = id4[q0 + t];
    // decode table: float2 index r within a 147-float2 row -> sph column + rbf word offset
    // (grid-strided: 147 > QPB-safe)
    for (int i = t; i < 147; i += QPB) {
        int c = i / 3;                 // sph-harm column 0..48
        int w = i - c * 3;             // float2 within 6-float group
        int l = (c >= 1) + (c >= 4) + (c >= 9) + (c >= 16) + (c >= 25) + (c >= 36); // LIDX[c]
        tab_s[i] = (c << 8) | (l * 6 + w * 2);
    }
    __syncthreads();

    // cooperative coalesced gather: 21 float2 per quad row from L2-resident g_rbf
    {
        int tot = nq * 21;
        for (int i = t; i < tot; i += QPB) {
            int q = i / 21, w = i - q * 21;
            int l = w / 3, jw = w - l * 3;
            const float2* src = (const float2*)(g_rbf + (size_t)e_s[q] * RBF_STRIDE + l * 8 + jw * 2);
            *(float2*)(rbf_s + q * RBF_ROW + l * 6 + jw * 2) = __ldg(src);
        }
    }

    // each thread computes the 49 sph-harm values for one quad
    if (t < nq) {
        float th = Alpha[q0 + t], ph = Theta[q0 + t];
        float st_, ct_;
        sincosf(th, &st_, &ct_);
        float* sp = sph_s + t * 49;
        float pmm = 1.0f;
#pragma unroll
        for (int m = 0; m < NUM_S; m++) {
            float cm, sm;
            if (m == 0) { cm = 1.0f; sm = 0.0f; }
            else sincosf((float)m * ph, &sm, &cm);
            float pa = pmm;
            {   // l = m
                int l = m;
                float k = P.CK[l][m];
                if (m == 0) sp[l * l] = k * pa;
                else { sp[l * l + m] = k * cm * pa; sp[(l + 1) * (l + 1) - m] = k * sm * pa; }
            }
            if (m < NUM_S - 1) {
                float pb = (2.0f * m + 1.0f) * ct_ * pa;
                {   // l = m+1
                    int l = m + 1;
                    float k = P.CK[l][m];
                    if (m == 0) sp[l * l] = k * pb;
                    else { sp[l * l + m] = k * cm * pb; sp[(l + 1) * (l + 1) - m] = k * sm * pb; }
                }
#pragma unroll
                for (int l = m + 2; l < NUM_S; l++) {
                    float pc = ((2.0f * l - 1.0f) * ct_ * pb - (float)(l + m - 1) * pa) / (float)(l - m);
                    pa = pb; pb = pc;
                    float k = P.CK[l][m];
                    if (m == 0) sp[l * l] = k * pc;
                    else { sp[l * l + m] = k * cm * pc; sp[(l + 1) * (l + 1) - m] = k * sm * pc; }
                }
            }
            pmm = (1.0f - 2.0f * (m + 1)) * st_ * pmm;
        }
    }
    __syncthreads();

    // phase B: iterate float2 elements of the output stream. Consecutive lanes
    // write consecutive 8B -> each warp STG.64 covers 256 contiguous bytes
    // (2 lines = minimal wavefronts). Exactly nq*147 elements, no tail.
    int total2 = nq * 147;
    float2* ob = (float2*)(out + (size_t)q0 * 294);
    for (int i = t; i < total2; i += QPB) {
        int q = i / 147;               // constant divisor -> mul.hi
        int r = i - q * 147;
        int pk = tab_s[r];
        float s = sph_s[q * 49 + (pk >> 8)];
        float2 rv = *(float2*)(rbf_s + q * RBF_ROW + (pk & 255));
        __stcs(ob + i, make_float2(s * rv.x, s * rv.y));
    }
}

extern "C" void kernel_launch(void* const* d_in, const int* in_sizes, int n_in,
                              void* d_out, int out_size) {
    const float* D   = (const float*)d_in[0];
    const float* Al  = (const float*)d_in[1];
    const float* Th  = (const float*)d_in[2];
    const int*   id4 = (const int*)d_in[3];
    float* out = (float*)d_out;
    int NE = in_sizes[0];
    int NQ = in_sizes[1];
    if (NE > MAX_EDGES) NE = MAX_EDGES;

    const HostConsts& H = host_consts();

    cudaFuncSetAttribute(k2_kernel, cudaFuncAttributeMaxDynamicSharedMemorySize, K2_SMEM);

    k1_kernel<<<(NE + 255) / 256, 256>>>(D, NE, H.p1);
    k2_kernel<<<(NQ + QPB - 1) / QPB, QPB, K2_SMEM>>>(Al, Th, id4, out, NQ, H.p2);
}

// round 6
// speedup vs baseline: 2.2954x; 1.1823x over previous
#include <cuda_runtime.h>
#include <cmath>

#define NUM_S 7
#define NUM_R 6
#define MAX_EDGES 200000
#define RBF_STRIDE 56   // g_rbf: 7 l-groups padded to 8 floats each (float4-friendly)

// Per-edge precomputed radial basis, padded layout [e][l][8] (j=0..5 valid).
__device__ float g_rbf[(size_t)MAX_EDGES * RBF_STRIDE];

struct K1Params { float Z[NUM_S][NUM_R]; float C[NUM_S][NUM_R]; };  // C = BNORM * cutoff^-1.5
struct K2Params { float CK[NUM_S][NUM_S]; };                        // K(l,m) (* sqrt2 for m>0)

// ---------------- host-side constant computation (pure CPU, double) ----------------
static double sph_jn_d(int n, double x) {
    double j0 = sin(x) / x;
    if (n == 0) return j0;
    double j1 = sin(x) / (x * x) - cos(x) / x;
    double jm1 = j0, jc = j1;
    for (int l = 1; l < n; l++) {
        double t = (2.0 * l + 1.0) / x * jc - jm1;
        jm1 = jc; jc = t;
    }
    return jc;
}

struct HostConsts { K1Params p1; K2Params p2; };

static HostConsts compute_consts() {
    const double PI = 3.14159265358979323846;
    double Z[NUM_S][NUM_R];
    double points[NUM_S + NUM_R];
    for (int k = 0; k < NUM_R; k++) Z[0][k] = (k + 1) * PI;
    int npts = NUM_R + NUM_S - 1;
    for (int i = 0; i < npts; i++) points[i] = (i + 1) * PI;
    double racines[NUM_S + NUM_R];
    for (int order = 1; order < NUM_S; order++) {
        int nroots = NUM_R + NUM_S - 1 - order;
        for (int j = 0; j < nroots; j++) {
            double a = points[j], b = points[j + 1];
            double fa = sph_jn_d(order, a);
            for (int it = 0; it < 80; it++) {
                double m = 0.5 * (a + b);
                double fm = sph_jn_d(order, m);
                if (fa * fm <= 0.0) b = m; else { a = m; fa = fm; }
            }
            racines[j] = 0.5 * (a + b);
        }
        for (int i = 0; i < nroots; i++) points[i] = racines[i];
        for (int k = 0; k < NUM_R; k++) Z[order][k] = racines[k];
    }
    HostConsts h;
    double norm_const = pow(1.0 / 5.0, 1.5);
    for (int l = 0; l < NUM_S; l++)
        for (int j = 0; j < NUM_R; j++) {
            double bn = 1.0 / sqrt(0.5 * sph_jn_d(l + 1, Z[l][j]) * sph_jn_d(l + 1, Z[l][j]));
            h.p1.Z[l][j] = (float)Z[l][j];
            h.p1.C[l][j] = (float)(bn * norm_const);
        }
    double fact[16]; fact[0] = 1.0;
    for (int i = 1; i < 16; i++) fact[i] = fact[i - 1] * i;
    for (int l = 0; l < NUM_S; l++)
        for (int m = 0; m <= l; m++) {
            double K = sqrt((2.0 * l + 1.0) / (4.0 * PI) * fact[l - m] / fact[l + m]);
            if (m > 0) K *= sqrt(2.0);
            h.p2.CK[l][m] = (float)K;
        }
    return h;
}

static const HostConsts& host_consts() {
    static HostConsts h = compute_consts();
    return h;
}

// ---------------- kernel 1: per-edge radial basis (42 values, padded to 56) ----------------
__global__ __launch_bounds__(256)
void k1_kernel(const float* __restrict__ D, int NE, K1Params P) {
    int e = blockIdx.x * blockDim.x + threadIdx.x;
    if (e >= NE) return;
    float d = D[e] * 0.2f;                    // D / CUTOFF
    float u;
    {
        float invd = 1.0f / d;
        float d2 = d * d, d4 = d2 * d2, d5 = d4 * d;
        u = invd + d5 * (-28.0f + d * (48.0f - 21.0f * d));
        if (!(d < 1.0f)) u = 0.0f;
    }
    float o[RBF_STRIDE];
#pragma unroll
    for (int l = 0; l < NUM_S; l++) {
#pragma unroll
        for (int j = 0; j < NUM_R; j++) {
            float x = d * P.Z[l][j];
            float s, c;
            sincosf(x, &s, &c);
            float invx = 1.0f / x;
            float cur = s * invx;             // j0
            if (l >= 1) {
                float prev = cur;
                cur = s * invx * invx - c * invx;   // j1 (same form as reference)
#pragma unroll
                for (int k = 1; k < l; k++) {
                    float nx = (2.0f * k + 1.0f) * invx * cur - prev;
                    prev = cur; cur = nx;
                }
            }
            o[l * 8 + j] = u * P.C[l][j] * cur;
        }
        o[l * 8 + 6] = 0.0f;
        o[l * 8 + 7] = 0.0f;
    }
    float4* dst = (float4*)(g_rbf + (size_t)e * RBF_STRIDE);
#pragma unroll
    for (int w = 0; w < 14; w++) dst[w] = ((float4*)o)[w];
}

// ---------------- kernel 2: sph + smem-staged rbf + fully coalesced stores ----------------
#define TPB 256                                // threads per block (8 warps)
#define QPB 128                                // quads per block
#define RBF_ROW 42                             // unpadded staged row: l*6+j
// smem: rbf [QPB][42] + sph [QPB][49] + tab[148] + e_s[QPB]  -> 47.8 KB, 4 CTAs/SM = 32 warps
#define K2_SMEM (QPB * RBF_ROW * 4 + QPB * 49 * 4 + 148 * 4 + QPB * 4)

__global__ __launch_bounds__(TPB)
void k2_kernel(const float* __restrict__ Alpha, const float* __restrict__ Theta,
               const int* __restrict__ id4, float* __restrict__ out,
               int NQ, K2Params P) {
    extern __shared__ __align__(16) float smem[];
    float* rbf_s = smem;                           // [QPB][42]
    float* sph_s = rbf_s + QPB * RBF_ROW;          // [QPB][49]
    int*   tab_s = (int*)(sph_s + QPB * 49);       // [147] packed (c<<8)|wordoff
    int*   e_s   = tab_s + 148;                    // [QPB]

    int t = threadIdx.x;
    int q0 = blockIdx.x * QPB;
    int nq = min(QPB, NQ - q0);

    if (t < nq) e_s[t] = id4[q0 + t];
    // decode table: float2 index r within a 147-float2 row -> sph column + rbf word offset
    if (t < 147) {
        int c = t / 3;                 // sph-harm column 0..48
        int w = t - c * 3;             // float2 within 6-float group
        int l = (c >= 1) + (c >= 4) + (c >= 9) + (c >= 16) + (c >= 25) + (c >= 36); // LIDX[c]
        tab_s[t] = (c << 8) | (l * 6 + w * 2);
    }
    __syncthreads();

    // cooperative coalesced gather: 21 float2 per quad row from L2-resident g_rbf
    {
        int tot = nq * 21;
        for (int i = t; i < tot; i += TPB) {
            int q = i / 21, w = i - q * 21;
            int l = w / 3, jw = w - l * 3;
            const float2* src = (const float2*)(g_rbf + (size_t)e_s[q] * RBF_STRIDE + l * 8 + jw * 2);
            *(float2*)(rbf_s + q * RBF_ROW + l * 6 + jw * 2) = __ldg(src);
        }
    }

    // threads [0, nq) each compute the 49 sph-harm values for one quad
    if (t < nq) {
        float th = Alpha[q0 + t], ph = Theta[q0 + t];
        float st_, ct_;
        sincosf(th, &st_, &ct_);
        float* sp = sph_s + t * 49;
        float pmm = 1.0f;
#pragma unroll
        for (int m = 0; m < NUM_S; m++) {
            float cm, sm;
            if (m == 0) { cm = 1.0f; sm = 0.0f; }
            else sincosf((float)m * ph, &sm, &cm);
            float pa = pmm;
            {   // l = m
                int l = m;
                float k = P.CK[l][m];
                if (m == 0) sp[l * l] = k * pa;
                else { sp[l * l + m] = k * cm * pa; sp[(l + 1) * (l + 1) - m] = k * sm * pa; }
            }
            if (m < NUM_S - 1) {
                float pb = (2.0f * m + 1.0f) * ct_ * pa;
                {   // l = m+1
                    int l = m + 1;
                    float k = P.CK[l][m];
                    if (m == 0) sp[l * l] = k * pb;
                    else { sp[l * l + m] = k * cm * pb; sp[(l + 1) * (l + 1) - m] = k * sm * pb; }
                }
#pragma unroll
                for (int l = m + 2; l < NUM_S; l++) {
                    float pc = ((2.0f * l - 1.0f) * ct_ * pb - (float)(l + m - 1) * pa) / (float)(l - m);
                    pa = pb; pb = pc;
                    float k = P.CK[l][m];
                    if (m == 0) sp[l * l] = k * pc;
                    else { sp[l * l + m] = k * cm * pc; sp[(l + 1) * (l + 1) - m] = k * sm * pc; }
                }
            }
            pmm = (1.0f - 2.0f * (m + 1)) * st_ * pmm;
        }
    }
    __syncthreads();

    // phase B: iterate float2 elements of the output stream. Consecutive lanes
    // write consecutive 8B -> each warp STG.64 covers 256 contiguous bytes.
    int total2 = nq * 147;
    float2* ob = (float2*)(out + (size_t)q0 * 294);
    for (int i = t; i < total2; i += TPB) {
        int q = i / 147;               // constant divisor -> mul.hi
        int r = i - q * 147;
        int pk = tab_s[r];
        float s = sph_s[q * 49 + (pk >> 8)];
        float2 rv = *(float2*)(rbf_s + q * RBF_ROW + (pk & 255));
        __stcs(ob + i, make_float2(s * rv.x, s * rv.y));
    }
}

extern "C" void kernel_launch(void* const* d_in, const int* in_sizes, int n_in,
                              void* d_out, int out_size) {
    const float* D   = (const float*)d_in[0];
    const float* Al  = (const float*)d_in[1];
    const float* Th  = (const float*)d_in[2];
    const int*   id4 = (const int*)d_in[3];
    float* out = (float*)d_out;
    int NE = in_sizes[0];
    int NQ = in_sizes[1];
    if (NE > MAX_EDGES) NE = MAX_EDGES;

    const HostConsts& H = host_consts();

    cudaFuncSetAttribute(k2_kernel, cudaFuncAttributeMaxDynamicSharedMemorySize, K2_SMEM);

    k1_kernel<<<(NE + 255) / 256, 256>>>(D, NE, H.p1);
    k2_kernel<<<(NQ + QPB - 1) / QPB, TPB, K2_SMEM>>>(Al, Th, id4, out, NQ, H.p2);
}

// round 7
// speedup vs baseline: 2.4565x; 1.0702x over previous
#include <cuda_runtime.h>
#include <cmath>

#define NUM_S 7
#define NUM_R 6
#define MAX_EDGES 200000
#define RBF_STRIDE 56   // g_rbf: 7 l-groups padded to 8 floats each (float4-friendly)

// Per-edge precomputed radial basis, padded layout [e][l][8] (j=0..5 valid).
__device__ float g_rbf[(size_t)MAX_EDGES * RBF_STRIDE];

struct K1Params { float Z[NUM_S][NUM_R]; float C[NUM_S][NUM_R]; };  // C = BNORM * cutoff^-1.5
struct K2Params { float CK[NUM_S][NUM_S]; };                        // K(l,m) (* sqrt2 for m>0)

// ---------------- host-side constant computation (pure CPU, double) ----------------
static double sph_jn_d(int n, double x) {
    double j0 = sin(x) / x;
    if (n == 0) return j0;
    double j1 = sin(x) / (x * x) - cos(x) / x;
    double jm1 = j0, jc = j1;
    for (int l = 1; l < n; l++) {
        double t = (2.0 * l + 1.0) / x * jc - jm1;
        jm1 = jc; jc = t;
    }
    return jc;
}

struct HostConsts { K1Params p1; K2Params p2; };

static HostConsts compute_consts() {
    const double PI = 3.14159265358979323846;
    double Z[NUM_S][NUM_R];
    double points[NUM_S + NUM_R];
    for (int k = 0; k < NUM_R; k++) Z[0][k] = (k + 1) * PI;
    int npts = NUM_R + NUM_S - 1;
    for (int i = 0; i < npts; i++) points[i] = (i + 1) * PI;
    double racines[NUM_S + NUM_R];
    for (int order = 1; order < NUM_S; order++) {
        int nroots = NUM_R + NUM_S - 1 - order;
        for (int j = 0; j < nroots; j++) {
            double a = points[j], b = points[j + 1];
            double fa = sph_jn_d(order, a);
            for (int it = 0; it < 80; it++) {
                double m = 0.5 * (a + b);
                double fm = sph_jn_d(order, m);
                if (fa * fm <= 0.0) b = m; else { a = m; fa = fm; }
            }
            racines[j] = 0.5 * (a + b);
        }
        for (int i = 0; i < nroots; i++) points[i] = racines[i];
        for (int k = 0; k < NUM_R; k++) Z[order][k] = racines[k];
    }
    HostConsts h;
    double norm_const = pow(1.0 / 5.0, 1.5);
    for (int l = 0; l < NUM_S; l++)
        for (int j = 0; j < NUM_R; j++) {
            double bn = 1.0 / sqrt(0.5 * sph_jn_d(l + 1, Z[l][j]) * sph_jn_d(l + 1, Z[l][j]));
            h.p1.Z[l][j] = (float)Z[l][j];
            h.p1.C[l][j] = (float)(bn * norm_const);
        }
    double fact[16]; fact[0] = 1.0;
    for (int i = 1; i < 16; i++) fact[i] = fact[i - 1] * i;
    for (int l = 0; l < NUM_S; l++)
        for (int m = 0; m <= l; m++) {
            double K = sqrt((2.0 * l + 1.0) / (4.0 * PI) * fact[l - m] / fact[l + m]);
            if (m > 0) K *= sqrt(2.0);
            h.p2.CK[l][m] = (float)K;
        }
    return h;
}

static const HostConsts& host_consts() {
    static HostConsts h = compute_consts();
    return h;
}

// ---------------- kernel 1: per-edge radial basis (42 values, padded to 56) ----------------
__global__ __launch_bounds__(256)
void k1_kernel(const float* __restrict__ D, int NE, K1Params P) {
    int e = blockIdx.x * blockDim.x + threadIdx.x;
    if (e >= NE) return;
    float d = D[e] * 0.2f;                    // D / CUTOFF
    float u;
    {
        float invd = 1.0f / d;
        float d2 = d * d, d4 = d2 * d2, d5 = d4 * d;
        u = invd + d5 * (-28.0f + d * (48.0f - 21.0f * d));
        if (!(d < 1.0f)) u = 0.0f;
    }
    float o[RBF_STRIDE];
#pragma unroll
    for (int l = 0; l < NUM_S; l++) {
#pragma unroll
        for (int j = 0; j < NUM_R; j++) {
            float x = d * P.Z[l][j];
            float s, c;
            sincosf(x, &s, &c);
            float invx = 1.0f / x;
            float cur = s * invx;             // j0
            if (l >= 1) {
                float prev = cur;
                cur = s * invx * invx - c * invx;   // j1 (same form as reference)
#pragma unroll
                for (int k = 1; k < l; k++) {
                    float nx = (2.0f * k + 1.0f) * invx * cur - prev;
                    prev = cur; cur = nx;
                }
            }
            o[l * 8 + j] = u * P.C[l][j] * cur;
        }
        o[l * 8 + 6] = 0.0f;
        o[l * 8 + 7] = 0.0f;
    }
    float4* dst = (float4*)(g_rbf + (size_t)e * RBF_STRIDE);
#pragma unroll
    for (int w = 0; w < 14; w++) dst[w] = ((float4*)o)[w];
}

// ---------------- kernel 2: sph + smem-staged rbf + fully coalesced stores ----------------
#define TPB 256                                // threads per block (8 warps)
#define QPB 64                                 // quads per block
#define RBF_ROW 42                             // unpadded staged row: l*6+j
// smem: rbf [64][42] + sph [64][49] + tab[148] + e_s[64] -> 23.6 KB
// => 8 CTAs/SM (thread-limited, 2048 thr) = 64 warps (~100% occ)
#define K2_SMEM (QPB * RBF_ROW * 4 + QPB * 49 * 4 + 148 * 4 + QPB * 4)

__global__ __launch_bounds__(TPB, 8)
void k2_kernel(const float* __restrict__ Alpha, const float* __restrict__ Theta,
               const int* __restrict__ id4, float* __restrict__ out,
               int NQ, K2Params P) {
    extern __shared__ __align__(16) float smem[];
    float* rbf_s = smem;                           // [QPB][42]
    float* sph_s = rbf_s + QPB * RBF_ROW;          // [QPB][49]
    int*   tab_s = (int*)(sph_s + QPB * 49);       // [147] packed (c<<8)|wordoff
    int*   e_s   = tab_s + 148;                    // [QPB]

    int t = threadIdx.x;
    int q0 = blockIdx.x * QPB;
    int nq = min(QPB, NQ - q0);

    if (t < nq) e_s[t] = id4[q0 + t];
    // decode table: float2 index r within a 147-float2 row -> sph column + rbf word offset
    if (t < 147) {
        int c = t / 3;                 // sph-harm column 0..48
        int w = t - c * 3;             // float2 within 6-float group
        int l = (c >= 1) + (c >= 4) + (c >= 9) + (c >= 16) + (c >= 25) + (c >= 36); // LIDX[c]
        tab_s[t] = (c << 8) | (l * 6 + w * 2);
    }
    __syncthreads();

    // cooperative coalesced gather: 21 float2 per quad row from L2-resident g_rbf
    {
        int tot = nq * 21;
        for (int i = t; i < tot; i += TPB) {
            int q = i / 21, w = i - q * 21;
            int l = w / 3, jw = w - l * 3;
            const float2* src = (const float2*)(g_rbf + (size_t)e_s[q] * RBF_STRIDE + l * 8 + jw * 2);
            *(float2*)(rbf_s + q * RBF_ROW + l * 6 + jw * 2) = __ldg(src);
        }
    }

    // threads [0, nq) each compute the 49 sph-harm values for one quad
    if (t < nq) {
        float th = Alpha[q0 + t], ph = Theta[q0 + t];
        float st_, ct_;
        sincosf(th, &st_, &ct_);
        float* sp = sph_s + t * 49;
        float pmm = 1.0f;
#pragma unroll
        for (int m = 0; m < NUM_S; m++) {
            float cm, sm;
            if (m == 0) { cm = 1.0f; sm = 0.0f; }
            else sincosf((float)m * ph, &sm, &cm);
            float pa = pmm;
            {   // l = m
                int l = m;
                float k = P.CK[l][m];
                if (m == 0) sp[l * l] = k * pa;
                else { sp[l * l + m] = k * cm * pa; sp[(l + 1) * (l + 1) - m] = k * sm * pa; }
            }
            if (m < NUM_S - 1) {
                float pb = (2.0f * m + 1.0f) * ct_ * pa;
                {   // l = m+1
                    int l = m + 1;
                    float k = P.CK[l][m];
                    if (m == 0) sp[l * l] = k * pb;
                    else { sp[l * l + m] = k * cm * pb; sp[(l + 1) * (l + 1) - m] = k * sm * pb; }
                }
#pragma unroll
                for (int l = m + 2; l < NUM_S; l++) {
                    float pc = ((2.0f * l - 1.0f) * ct_ * pb - (float)(l + m - 1) * pa) / (float)(l - m);
                    pa = pb; pb = pc;
                    float k = P.CK[l][m];
                    if (m == 0) sp[l * l] = k * pc;
                    else { sp[l * l + m] = k * cm * pc; sp[(l + 1) * (l + 1) - m] = k * sm * pc; }
                }
            }
            pmm = (1.0f - 2.0f * (m + 1)) * st_ * pmm;
        }
    }
    __syncthreads();

    // phase B: iterate float2 elements of the output stream. Consecutive lanes
    // write consecutive 8B -> each warp STG.64 covers 256 contiguous bytes.
    int total2 = nq * 147;
    float2* ob = (float2*)(out + (size_t)q0 * 294);
    for (int i = t; i < total2; i += TPB) {
        int q = i / 147;               // constant divisor -> mul.hi
        int r = i - q * 147;
        int pk = tab_s[r];
        float s = sph_s[q * 49 + (pk >> 8)];
        float2 rv = *(float2*)(rbf_s + q * RBF_ROW + (pk & 255));
        __stcs(ob + i, make_float2(s * rv.x, s * rv.y));
    }
}

extern "C" void kernel_launch(void* const* d_in, const int* in_sizes, int n_in,
                              void* d_out, int out_size) {
    const float* D   = (const float*)d_in[0];
    const float* Al  = (const float*)d_in[1];
    const float* Th  = (const float*)d_in[2];
    const int*   id4 = (const int*)d_in[3];
    float* out = (float*)d_out;
    int NE = in_sizes[0];
    int NQ = in_sizes[1];
    if (NE > MAX_EDGES) NE = MAX_EDGES;

    const HostConsts& H = host_consts();

    cudaFuncSetAttribute(k2_kernel, cudaFuncAttributeMaxDynamicSharedMemorySize, K2_SMEM);

    k1_kernel<<<(NE + 255) / 256, 256>>>(D, NE, H.p1);
    k2_kernel<<<(NQ + QPB - 1) / QPB, TPB, K2_SMEM>>>(Al, Th, id4, out, NQ, H.p2);
}

// round 8
// speedup vs baseline: 2.5184x; 1.0252x over previous
#include <cuda_runtime.h>
#include <cmath>

#define NUM_S 7
#define NUM_R 6
#define MAX_EDGES 200000
#define RBF_STRIDE 56   // g_rbf: 7 l-groups padded to 8 floats each (float4-friendly)

// Per-edge precomputed radial basis, padded layout [e][l][8] (j=0..5 valid).
__device__ float g_rbf[(size_t)MAX_EDGES * RBF_STRIDE];

struct K1Params { float Z[NUM_S][NUM_R]; float C[NUM_S][NUM_R]; };  // C = BNORM * cutoff^-1.5
struct K2Params { float CK[NUM_S][NUM_S]; };                        // K(l,m) (* sqrt2 for m>0)

// ---------------- host-side constant computation (pure CPU, double) ----------------
static double sph_jn_d(int n, double x) {
    double j0 = sin(x) / x;
    if (n == 0) return j0;
    double j1 = sin(x) / (x * x) - cos(x) / x;
    double jm1 = j0, jc = j1;
    for (int l = 1; l < n; l++) {
        double t = (2.0 * l + 1.0) / x * jc - jm1;
        jm1 = jc; jc = t;
    }
    return jc;
}

struct HostConsts { K1Params p1; K2Params p2; };

static HostConsts compute_consts() {
    const double PI = 3.14159265358979323846;
    double Z[NUM_S][NUM_R];
    double points[NUM_S + NUM_R];
    for (int k = 0; k < NUM_R; k++) Z[0][k] = (k + 1) * PI;
    int npts = NUM_R + NUM_S - 1;
    for (int i = 0; i < npts; i++) points[i] = (i + 1) * PI;
    double racines[NUM_S + NUM_R];
    for (int order = 1; order < NUM_S; order++) {
        int nroots = NUM_R + NUM_S - 1 - order;
        for (int j = 0; j < nroots; j++) {
            double a = points[j], b = points[j + 1];
            double fa = sph_jn_d(order, a);
            for (int it = 0; it < 80; it++) {
                double m = 0.5 * (a + b);
                double fm = sph_jn_d(order, m);
                if (fa * fm <= 0.0) b = m; else { a = m; fa = fm; }
            }
            racines[j] = 0.5 * (a + b);
        }
        for (int i = 0; i < nroots; i++) points[i] = racines[i];
        for (int k = 0; k < NUM_R; k++) Z[order][k] = racines[k];
    }
    HostConsts h;
    double norm_const = pow(1.0 / 5.0, 1.5);
    for (int l = 0; l < NUM_S; l++)
        for (int j = 0; j < NUM_R; j++) {
            double bn = 1.0 / sqrt(0.5 * sph_jn_d(l + 1, Z[l][j]) * sph_jn_d(l + 1, Z[l][j]));
            h.p1.Z[l][j] = (float)Z[l][j];
            h.p1.C[l][j] = (float)(bn * norm_const);
        }
    double fact[16]; fact[0] = 1.0;
    for (int i = 1; i < 16; i++) fact[i] = fact[i - 1] * i;
    for (int l = 0; l < NUM_S; l++)
        for (int m = 0; m <= l; m++) {
            double K = sqrt((2.0 * l + 1.0) / (4.0 * PI) * fact[l - m] / fact[l + m]);
            if (m > 0) K *= sqrt(2.0);
            h.p2.CK[l][m] = (float)K;
        }
    return h;
}

static const HostConsts& host_consts() {
    static HostConsts h = compute_consts();
    return h;
}

// ---------------- kernel 1: per-(edge,j) radial basis, smem-staged coalesced write ----
#define EPB 42                                  // edges per block
#define TPB1 (EPB * 6)                          // 252 threads, one per (edge, j)

__global__ __launch_bounds__(TPB1)
void k1_kernel(const float* __restrict__ D, int NE, K1Params P) {
    __shared__ __align__(16) float sm_o[EPB * RBF_STRIDE];   // 9.4 KB

    int t = threadIdx.x;
    int el = t / 6;                   // local edge 0..41
    int j  = t - el * 6;              // radial index 0..5
    int be = blockIdx.x * EPB;        // first edge of block
    int e  = be + el;

    if (e < NE) {
        float d = D[e] * 0.2f;        // D / CUTOFF (broadcast load across 6 lanes)
        float u;
        {
            float invd = 1.0f / d;
            float d2 = d * d, d4 = d2 * d2, d5 = d4 * d;
            u = invd + d5 * (-28.0f + d * (48.0f - 21.0f * d));
            if (!(d < 1.0f)) u = 0.0f;
        }
#pragma unroll
        for (int l = 0; l < NUM_S; l++) {
            float x = d * P.Z[l][j];
            float s, c;
            sincosf(x, &s, &c);
            float invx = 1.0f / x;
            float cur = s * invx;                      // j0
            if (l >= 1) {
                float prev = cur;
                cur = s * invx * invx - c * invx;      // j1 (same form as reference)
#pragma unroll
                for (int k = 1; k < l; k++) {
                    float nx = (2.0f * k + 1.0f) * invx * cur - prev;
                    prev = cur; cur = nx;
                }
            }
            sm_o[el * RBF_STRIDE + l * 8 + j] = u * P.C[l][j] * cur;
            if (j < 2) sm_o[el * RBF_STRIDE + l * 8 + 6 + j] = 0.0f;   // pad words
        }
    }
    __syncthreads();

    // coalesced copy: valid edges' rows are contiguous in g_rbf
    int nvalid = min(EPB, NE - be);
    if (nvalid > 0) {
        int tot4 = nvalid * 14;                        // float4s
        const float4* src = (const float4*)sm_o;
        float4* dst = (float4*)(g_rbf + (size_t)be * RBF_STRIDE);
        for (int i = t; i < tot4; i += TPB1) dst[i] = src[i];
    }
}

// ---------------- kernel 2: sph + smem-staged rbf + fully coalesced stores ----------------
#define TPB 256                                // threads per block (8 warps)
#define QPB 64                                 // quads per block
#define RBF_ROW 42                             // unpadded staged row: l*6+j
// smem: rbf [64][42] + sph [64][49] + tab[148] + e_s[64] -> 23.6 KB
// => 8 CTAs/SM (thread-limited, 2048 thr) = 64 warps (~100% occ)
#define K2_SMEM (QPB * RBF_ROW * 4 + QPB * 49 * 4 + 148 * 4 + QPB * 4)

__global__ __launch_bounds__(TPB, 8)
void k2_kernel(const float* __restrict__ Alpha, const float* __restrict__ Theta,
               const int* __restrict__ id4, float* __restrict__ out,
               int NQ, K2Params P) {
    extern __shared__ __align__(16) float smem[];
    float* rbf_s = smem;                           // [QPB][42]
    float* sph_s = rbf_s + QPB * RBF_ROW;          // [QPB][49]
    int*   tab_s = (int*)(sph_s + QPB * 49);       // [147] packed (c<<8)|wordoff
    int*   e_s   = tab_s + 148;                    // [QPB]

    int t = threadIdx.x;
    int q0 = blockIdx.x * QPB;
    int nq = min(QPB, NQ - q0);

    if (t < nq) e_s[t] = id4[q0 + t];
    // decode table: float2 index r within a 147-float2 row -> sph column + rbf word offset
    if (t < 147) {
        int c = t / 3;                 // sph-harm column 0..48
        int w = t - c * 3;             // float2 within 6-float group
        int l = (c >= 1) + (c >= 4) + (c >= 9) + (c >= 16) + (c >= 25) + (c >= 36); // LIDX[c]
        tab_s[t] = (c << 8) | (l * 6 + w * 2);
    }
    __syncthreads();

    // cooperative coalesced gather: 21 float2 per quad row from L2-resident g_rbf
    {
        int tot = nq * 21;
        for (int i = t; i < tot; i += TPB) {
            int q = i / 21, w = i - q * 21;
            int l = w / 3, jw = w - l * 3;
            const float2* src = (const float2*)(g_rbf + (size_t)e_s[q] * RBF_STRIDE + l * 8 + jw * 2);
            *(float2*)(rbf_s + q * RBF_ROW + l * 6 + jw * 2) = __ldg(src);
        }
    }

    // threads [0, nq) each compute the 49 sph-harm values for one quad
    if (t < nq) {
        float th = Alpha[q0 + t], ph = Theta[q0 + t];
        float st_, ct_;
        sincosf(th, &st_, &ct_);
        float* sp = sph_s + t * 49;
        float pmm = 1.0f;
#pragma unroll
        for (int m = 0; m < NUM_S; m++) {
            float cm, sm;
            if (m == 0) { cm = 1.0f; sm = 0.0f; }
            else sincosf((float)m * ph, &sm, &cm);
            float pa = pmm;
            {   // l = m
                int l = m;
                float k = P.CK[l][m];
                if (m == 0) sp[l * l] = k * pa;
                else { sp[l * l + m] = k * cm * pa; sp[(l + 1) * (l + 1) - m] = k * sm * pa; }
            }
            if (m < NUM_S - 1) {
                float pb = (2.0f * m + 1.0f) * ct_ * pa;
                {   // l = m+1
                    int l = m + 1;
                    float k = P.CK[l][m];
                    if (m == 0) sp[l * l] = k * pb;
                    else { sp[l * l + m] = k * cm * pb; sp[(l + 1) * (l + 1) - m] = k * sm * pb; }
                }
#pragma unroll
                for (int l = m + 2; l < NUM_S; l++) {
                    float pc = ((2.0f * l - 1.0f) * ct_ * pb - (float)(l + m - 1) * pa) / (float)(l - m);
                    pa = pb; pb = pc;
                    float k = P.CK[l][m];
                    if (m == 0) sp[l * l] = k * pc;
                    else { sp[l * l + m] = k * cm * pc; sp[(l + 1) * (l + 1) - m] = k * sm * pc; }
                }
            }
            pmm = (1.0f - 2.0f * (m + 1)) * st_ * pmm;
        }
    }
    __syncthreads();

    // phase B: iterate float2 elements of the output stream, unrolled x2 with
    // front-batched loads (independent iterations -> MLP 2 per warp).
    // Consecutive lanes write consecutive 8B -> warp STG.64 = 256 contiguous B.
    int total2 = nq * 147;
    float2* ob = (float2*)(out + (size_t)q0 * 294);
    int i = t;
    for (; i + TPB < total2; i += 2 * TPB) {
        int ia = i, ib = i + TPB;
        int qa = ia / 147, ra = ia - qa * 147;
        int qb = ib / 147, rb = ib - qb * 147;
        int pka = tab_s[ra];
        int pkb = tab_s[rb];
        float sa = sph_s[qa * 49 + (pka >> 8)];
        float sb = sph_s[qb * 49 + (pkb >> 8)];
        float2 rva = *(float2*)(rbf_s + qa * RBF_ROW + (pka & 255));
        float2 rvb = *(float2*)(rbf_s + qb * RBF_ROW + (pkb & 255));
        __stcs(ob + ia, make_float2(sa * rva.x, sa * rva.y));
        __stcs(ob + ib, make_float2(sb * rvb.x, sb * rvb.y));
    }
    if (i < total2) {
        int q = i / 147, r = i - q * 147;
        int pk = tab_s[r];
        float s = sph_s[q * 49 + (pk >> 8)];
        float2 rv = *(float2*)(rbf_s + q * RBF_ROW + (pk & 255));
        __stcs(ob + i, make_float2(s * rv.x, s * rv.y));
    }
}

extern "C" void kernel_launch(void* const* d_in, const int* in_sizes, int n_in,
                              void* d_out, int out_size) {
    const float* D   = (const float*)d_in[0];
    const float* Al  = (const float*)d_in[1];
    const float* Th  = (const float*)d_in[2];
    const int*   id4 = (const int*)d_in[3];
    float* out = (float*)d_out;
    int NE = in_sizes[0];
    int NQ = in_sizes[1];
    if (NE > MAX_EDGES) NE = MAX_EDGES;

    const HostConsts& H = host_consts();

    cudaFuncSetAttribute(k2_kernel, cudaFuncAttributeMaxDynamicSharedMemorySize, K2_SMEM);

    k1_kernel<<<(NE + EPB - 1) / EPB, TPB1>>>(D, NE, H.p1);
    k2_kernel<<<(NQ + QPB - 1) / QPB, TPB, K2_SMEM>>>(Al, Th, id4, out, NQ, H.p2);
}

// round 9
// speedup vs baseline: 3.4431x; 1.3672x over previous
#include <cuda_runtime.h>
#include <cmath>

#define NUM_S 7
#define NUM_R 6

struct KParams {
    float Z[NUM_S][NUM_R];   // bessel zeros
    float C[NUM_S][NUM_R];   // BNORM * cutoff^-1.5
    float CK[NUM_S][NUM_S];  // sph-harm K(l,m) (* sqrt2 for m>0)
};

// ---------------- host-side constant computation (pure CPU, double) ----------------
static double sph_jn_d(int n, double x) {
    double j0 = sin(x) / x;
    if (n == 0) return j0;
    double j1 = sin(x) / (x * x) - cos(x) / x;
    double jm1 = j0, jc = j1;
    for (int l = 1; l < n; l++) {
        double t = (2.0 * l + 1.0) / x * jc - jm1;
        jm1 = jc; jc = t;
    }
    return jc;
}

static KParams compute_consts() {
    const double PI = 3.14159265358979323846;
    double Z[NUM_S][NUM_R];
    double points[NUM_S + NUM_R];
    for (int k = 0; k < NUM_R; k++) Z[0][k] = (k + 1) * PI;
    int npts = NUM_R + NUM_S - 1;
    for (int i = 0; i < npts; i++) points[i] = (i + 1) * PI;
    double racines[NUM_S + NUM_R];
    for (int order = 1; order < NUM_S; order++) {
        int nroots = NUM_R + NUM_S - 1 - order;
        for (int j = 0; j < nroots; j++) {
            double a = points[j], b = points[j + 1];
            double fa = sph_jn_d(order, a);
            for (int it = 0; it < 80; it++) {
                double m = 0.5 * (a + b);
                double fm = sph_jn_d(order, m);
                if (fa * fm <= 0.0) b = m; else { a = m; fa = fm; }
            }
            racines[j] = 0.5 * (a + b);
        }
        for (int i = 0; i < nroots; i++) points[i] = racines[i];
        for (int k = 0; k < NUM_R; k++) Z[order][k] = racines[k];
    }
    KParams h;
    double norm_const = pow(1.0 / 5.0, 1.5);
    for (int l = 0; l < NUM_S; l++)
        for (int j = 0; j < NUM_R; j++) {
            double bn = 1.0 / sqrt(0.5 * sph_jn_d(l + 1, Z[l][j]) * sph_jn_d(l + 1, Z[l][j]));
            h.Z[l][j] = (float)Z[l][j];
            h.C[l][j] = (float)(bn * norm_const);
        }
    double fact[16]; fact[0] = 1.0;
    for (int i = 1; i < 16; i++) fact[i] = fact[i - 1] * i;
    for (int l = 0; l < NUM_S; l++)
        for (int m = 0; m <= l; m++) {
            double K = sqrt((2.0 * l + 1.0) / (4.0 * PI) * fact[l - m] / fact[l + m]);
            if (m > 0) K *= sqrt(2.0);
            h.CK[l][m] = (float)K;
        }
    return h;
}

static const KParams& host_consts() {
    static KParams h = compute_consts();
    return h;
}

// ---------------- single fused kernel ----------------
#define TPB 256                                // 8 warps
#define QPB 64                                 // quads per block
#define RBF_ROW 42                             // rbf row: l*6+j
// smem: rbf [64][42] + sph [64][49] + tab[148] + d[64] + u[64]  ~= 24.4 KB
// => 8 CTAs/SM (thread-limited 2048 thr) = 64 warps
#define K_SMEM (QPB * RBF_ROW * 4 + QPB * 49 * 4 + 148 * 4 + QPB * 4 + QPB * 4)

__global__ __launch_bounds__(TPB, 8)
void fused_kernel(const float* __restrict__ D,
                  const float* __restrict__ Alpha, const float* __restrict__ Theta,
                  const int* __restrict__ id4, float* __restrict__ out,
                  int NQ, KParams P) {
    extern __shared__ __align__(16) float smem[];
    float* rbf_s = smem;                           // [QPB][42]
    float* sph_s = rbf_s + QPB * RBF_ROW;          // [QPB][49]
    int*   tab_s = (int*)(sph_s + QPB * 49);       // [147] packed (c<<8)|wordoff
    float* d_s   = (float*)(tab_s + 148);          // [QPB] scaled distance
    float* u_s   = d_s + QPB;                      // [QPB] envelope u(d)

    int t = threadIdx.x;
    int q0 = blockIdx.x * QPB;
    int nq = min(QPB, NQ - q0);

    // phase 0: per-quad distance + envelope; decode table
    if (t < nq) {
        int e = __ldg(id4 + q0 + t);
        float d = __ldg(D + e) * 0.2f;             // D / CUTOFF
        float invd = 1.0f / d;
        float d2 = d * d, d4 = d2 * d2, d5 = d4 * d;
        float u = invd + d5 * (-28.0f + d * (48.0f - 21.0f * d));
        if (!(d < 1.0f)) u = 0.0f;
        d_s[t] = d;
        u_s[t] = u;
    }
    if (t < 147) {
        int c = t / 3;                 // sph-harm column 0..48
        int w = t - c * 3;             // float2 within 6-float group
        int l = (c >= 1) + (c >= 4) + (c >= 9) + (c >= 16) + (c >= 25) + (c >= 36); // LIDX[c]
        tab_s[t] = (c << 8) | (l * 6 + w * 2);
    }
    __syncthreads();

    // phase A: fused rbf + sph compute.
    // threads 0..191: rbf items (q, j), 2 iterations each (nq*6 <= 384)
    // threads 192..255: sph for quad (t - 192)
    if (t < 192) {
        for (int i = t; i < nq * 6; i += 192) {
            int q = i / 6, j = i - q * 6;
            float d = d_s[q];
            float uc = u_s[q];
            float* rrow = rbf_s + q * RBF_ROW + j;
#pragma unroll
            for (int l = 0; l < NUM_S; l++) {
                float x = d * P.Z[l][j];
                float s, c;
                sincosf(x, &s, &c);
                float invx = 1.0f / x;
                float cur = s * invx;                      // j0
                if (l >= 1) {
                    float prev = cur;
                    cur = s * invx * invx - c * invx;      // j1 (same form as reference)
#pragma unroll
                    for (int k = 1; k < l; k++) {
                        float nx = (2.0f * k + 1.0f) * invx * cur - prev;
                        prev = cur; cur = nx;
                    }
                }
                rrow[l * 6] = uc * P.C[l][j] * cur;
            }
        }
    } else {
        int q = t - 192;
        if (q < nq) {
            float th = __ldg(Alpha + q0 + q), ph = __ldg(Theta + q0 + q);
            float st_, ct_;
            sincosf(th, &st_, &ct_);
            float* sp = sph_s + q * 49;
            float pmm = 1.0f;
#pragma unroll
            for (int m = 0; m < NUM_S; m++) {
                float cm, sm;
                if (m == 0) { cm = 1.0f; sm = 0.0f; }
                else sincosf((float)m * ph, &sm, &cm);
                float pa = pmm;
                {   // l = m
                    int l = m;
                    float k = P.CK[l][m];
                    if (m == 0) sp[l * l] = k * pa;
                    else { sp[l * l + m] = k * cm * pa; sp[(l + 1) * (l + 1) - m] = k * sm * pa; }
                }
                if (m < NUM_S - 1) {
                    float pb = (2.0f * m + 1.0f) * ct_ * pa;
                    {   // l = m+1
                        int l = m + 1;
                        float k = P.CK[l][m];
                        if (m == 0) sp[l * l] = k * pb;
                        else { sp[l * l + m] = k * cm * pb; sp[(l + 1) * (l + 1) - m] = k * sm * pb; }
                    }
#pragma unroll
                    for (int l = m + 2; l < NUM_S; l++) {
                        float pc = ((2.0f * l - 1.0f) * ct_ * pb - (float)(l + m - 1) * pa) / (float)(l - m);
                        pa = pb; pb = pc;
                        float k = P.CK[l][m];
                        if (m == 0) sp[l * l] = k * pc;
                        else { sp[l * l + m] = k * cm * pc; sp[(l + 1) * (l + 1) - m] = k * sm * pc; }
                    }
                }
                pmm = (1.0f - 2.0f * (m + 1)) * st_ * pmm;
            }
        }
    }
    __syncthreads();

    // phase B: iterate float2 elements of the output stream, unrolled x2 with
    // front-batched loads. Consecutive lanes write consecutive 8B -> warp
    // STG.64 = 256 contiguous B (minimal store wavefronts).
    int total2 = nq * 147;
    float2* ob = (float2*)(out + (size_t)q0 * 294);
    int i = t;
    for (; i + TPB < total2; i += 2 * TPB) {
        int ia = i, ib = i + TPB;
        int qa = ia / 147, ra = ia - qa * 147;
        int qb = ib / 147, rb = ib - qb * 147;
        int pka = tab_s[ra];
        int pkb = tab_s[rb];
        float sa = sph_s[qa * 49 + (pka >> 8)];
        float sb = sph_s[qb * 49 + (pkb >> 8)];
        float2 rva = *(float2*)(rbf_s + qa * RBF_ROW + (pka & 255));
        float2 rvb = *(float2*)(rbf_s + qb * RBF_ROW + (pkb & 255));
        __stcs(ob + ia, make_float2(sa * rva.x, sa * rva.y));
        __stcs(ob + ib, make_float2(sb * rvb.x, sb * rvb.y));
    }
    if (i < total2) {
        int q = i / 147, r = i - q * 147;
        int pk = tab_s[r];
        float s = sph_s[q * 49 + (pk >> 8)];
        float2 rv = *(float2*)(rbf_s + q * RBF_ROW + (pk & 255));
        __stcs(ob + i, make_float2(s * rv.x, s * rv.y));
    }
}

extern "C" void kernel_launch(void* const* d_in, const int* in_sizes, int n_in,
                              void* d_out, int out_size) {
    const float* D   = (const float*)d_in[0];
    const float* Al  = (const float*)d_in[1];
    const float* Th  = (const float*)d_in[2];
    const int*   id4 = (const int*)d_in[3];
    float* out = (float*)d_out;
    int NQ = in_sizes[1];

    const KParams& H = host_consts();

    cudaFuncSetAttribute(fused_kernel, cudaFuncAttributeMaxDynamicSharedMemorySize, K_SMEM);

    fused_kernel<<<(NQ + QPB - 1) / QPB, TPB, K_SMEM>>>(D, Al, Th, id4, out, NQ, H);
}

// round 10
// speedup vs baseline: 3.8237x; 1.1105x over previous
#include <cuda_runtime.h>
#include <cmath>

#define NUM_S 7
#define NUM_R 6

struct KParams {
    float Z[NUM_S][NUM_R];   // bessel zeros
    float C[NUM_S][NUM_R];   // BNORM * cutoff^-1.5
    float CK[NUM_S][NUM_S];  // sph-harm K(l,m) (* sqrt2 for m>0)
};

// ---------------- host-side constant computation (pure CPU, double) ----------------
static double sph_jn_d(int n, double x) {
    double j0 = sin(x) / x;
    if (n == 0) return j0;
    double j1 = sin(x) / (x * x) - cos(x) / x;
    double jm1 = j0, jc = j1;
    for (int l = 1; l < n; l++) {
        double t = (2.0 * l + 1.0) / x * jc - jm1;
        jm1 = jc; jc = t;
    }
    return jc;
}

static KParams compute_consts() {
    const double PI = 3.14159265358979323846;
    double Z[NUM_S][NUM_R];
    double points[NUM_S + NUM_R];
    for (int k = 0; k < NUM_R; k++) Z[0][k] = (k + 1) * PI;
    int npts = NUM_R + NUM_S - 1;
    for (int i = 0; i < npts; i++) points[i] = (i + 1) * PI;
    double racines[NUM_S + NUM_R];
    for (int order = 1; order < NUM_S; order++) {
        int nroots = NUM_R + NUM_S - 1 - order;
        for (int j = 0; j < nroots; j++) {
            double a = points[j], b = points[j + 1];
            double fa = sph_jn_d(order, a);
            for (int it = 0; it < 80; it++) {
                double m = 0.5 * (a + b);
                double fm = sph_jn_d(order, m);
                if (fa * fm <= 0.0) b = m; else { a = m; fa = fm; }
            }
            racines[j] = 0.5 * (a + b);
        }
        for (int i = 0; i < nroots; i++) points[i] = racines[i];
        for (int k = 0; k < NUM_R; k++) Z[order][k] = racines[k];
    }
    KParams h;
    double norm_const = pow(1.0 / 5.0, 1.5);
    for (int l = 0; l < NUM_S; l++)
        for (int j = 0; j < NUM_R; j++) {
            double bn = 1.0 / sqrt(0.5 * sph_jn_d(l + 1, Z[l][j]) * sph_jn_d(l + 1, Z[l][j]));
            h.Z[l][j] = (float)Z[l][j];
            h.C[l][j] = (float)(bn * norm_const);
        }
    double fact[16]; fact[0] = 1.0;
    for (int i = 1; i < 16; i++) fact[i] = fact[i - 1] * i;
    for (int l = 0; l < NUM_S; l++)
        for (int m = 0; m <= l; m++) {
            double K = sqrt((2.0 * l + 1.0) / (4.0 * PI) * fact[l - m] / fact[l + m]);
            if (m > 0) K *= sqrt(2.0);
            h.CK[l][m] = (float)K;
        }
    return h;
}

static const KParams& host_consts() {
    static KParams h = compute_consts();
    return h;
}

// ---------------- fast branch-free sincos, valid for x in [0, ~100] ----------------
__device__ __forceinline__ void fast_sincos(float x, float& so, float& co) {
    float kf = rintf(x * 0.63661977236758134f);          // x * 2/pi
    int   qi = (int)kf;
    float r  = fmaf(kf, -1.5707962513f, x);              // PIO2_HI
    r        = fmaf(kf, -7.54978942e-8f, r);             // PIO2_LO
    float r2 = r * r;
    // cephes minimax on [-pi/4, pi/4]
    float ps = fmaf(r2, fmaf(r2, -1.9515295891e-4f, 8.3321608736e-3f), -1.6666654611e-1f);
    ps = fmaf(r * r2, ps, r);
    float pc = fmaf(r2, fmaf(r2, fmaf(r2, 2.443315711809948e-5f, -1.388731625493765e-3f),
                             4.166664568298827e-2f), -0.5f);
    pc = fmaf(r2, pc, 1.0f);
    bool swap = qi & 1;
    float ss = swap ? pc : ps;
    float cc = swap ? ps : pc;
    if ((qi >> 1) & 1) ss = -ss;
    if (((qi + 1) >> 1) & 1) cc = -cc;
    so = ss; co = cc;
}

// ---------------- single fused kernel ----------------
#define TPB 256                                // 8 warps
#define QPB 64                                 // quads per block
#define RBF_ROW 42                             // rbf row: l*6+j
#define K_SMEM (QPB * RBF_ROW * 4 + QPB * 49 * 4 + 148 * 4 + QPB * 4 + QPB * 4)

__global__ __launch_bounds__(TPB, 8)
void fused_kernel(const float* __restrict__ D,
                  const float* __restrict__ Alpha, const float* __restrict__ Theta,
                  const int* __restrict__ id4, float* __restrict__ out,
                  int NQ, KParams P) {
    extern __shared__ __align__(16) float smem[];
    float* rbf_s = smem;                           // [QPB][42]
    float* sph_s = rbf_s + QPB * RBF_ROW;          // [QPB][49]
    int*   tab_s = (int*)(sph_s + QPB * 49);       // [147] packed (c<<8)|wordoff
    float* d_s   = (float*)(tab_s + 148);          // [QPB] scaled distance
    float* u_s   = d_s + QPB;                      // [QPB] envelope u(d)

    int t = threadIdx.x;
    int q0 = blockIdx.x * QPB;
    int nq = min(QPB, NQ - q0);

    // phase 0: per-quad distance + envelope; decode table
    if (t < nq) {
        int e = __ldg(id4 + q0 + t);
        float d = __ldg(D + e) * 0.2f;             // D / CUTOFF
        float invd = 1.0f / d;
        float d2 = d * d, d4 = d2 * d2, d5 = d4 * d;
        float u = invd + d5 * (-28.0f + d * (48.0f - 21.0f * d));
        if (!(d < 1.0f)) u = 0.0f;
        d_s[t] = d;
        u_s[t] = u;
    }
    if (t < 147) {
        int c = t / 3;                 // sph-harm column 0..48
        int w = t - c * 3;             // float2 within 6-float group
        int l = (c >= 1) + (c >= 4) + (c >= 9) + (c >= 16) + (c >= 25) + (c >= 36); // LIDX[c]
        tab_s[t] = (c << 8) | (l * 6 + w * 2);
    }
    __syncthreads();

    // phase A: fused rbf + sph compute.
    if (t < 192) {
        // rbf items (q, j)
        for (int i = t; i < nq * 6; i += 192) {
            int q = i / 6, j = i - q * 6;
            float d = d_s[q];
            float uc = u_s[q];
            float* rrow = rbf_s + q * RBF_ROW + j;
#pragma unroll
            for (int l = 0; l < NUM_S; l++) {
                float x = d * P.Z[l][j];
                float s, c;
                fast_sincos(x, s, c);
                float invx = 1.0f / x;
                float cur = s * invx;                      // j0
                if (l >= 1) {
                    float prev = cur;
                    cur = s * invx * invx - c * invx;      // j1 (same form as reference)
#pragma unroll
                    for (int k = 1; k < l; k++) {
                        float nx = (2.0f * k + 1.0f) * invx * cur - prev;
                        prev = cur; cur = nx;
                    }
                }
                rrow[l * 6] = uc * P.C[l][j] * cur;
            }
        }
    } else {
        int q = t - 192;
        if (q < nq) {
            float th = __ldg(Alpha + q0 + q), ph = __ldg(Theta + q0 + q);
            float st_, ct_;
            fast_sincos(th, st_, ct_);
            float* sp = sph_s + q * 49;
            float pmm = 1.0f;
#pragma unroll
            for (int m = 0; m < NUM_S; m++) {
                float cm, sm;
                if (m == 0) { cm = 1.0f; sm = 0.0f; }
                else fast_sincos((float)m * ph, sm, cm);
                float pa = pmm;
                {   // l = m
                    int l = m;
                    float k = P.CK[l][m];
                    if (m == 0) sp[l * l] = k * pa;
                    else { sp[l * l + m] = k * cm * pa; sp[(l + 1) * (l + 1) - m] = k * sm * pa; }
                }
                if (m < NUM_S - 1) {
                    float pb = (2.0f * m + 1.0f) * ct_ * pa;
                    {   // l = m+1
                        int l = m + 1;
                        float k = P.CK[l][m];
                        if (m == 0) sp[l * l] = k * pb;
                        else { sp[l * l + m] = k * cm * pb; sp[(l + 1) * (l + 1) - m] = k * sm * pb; }
                    }
#pragma unroll
                    for (int l = m + 2; l < NUM_S; l++) {
                        float pc = ((2.0f * l - 1.0f) * ct_ * pb - (float)(l + m - 1) * pa)
                                   * (1.0f / (float)(l - m));   // compile-time reciprocal
                        pa = pb; pb = pc;
                        float k = P.CK[l][m];
                        if (m == 0) sp[l * l] = k * pc;
                        else { sp[l * l + m] = k * cm * pc; sp[(l + 1) * (l + 1) - m] = k * sm * pc; }
                    }
                }
                pmm = (1.0f - 2.0f * (m + 1)) * st_ * pmm;
            }
        }
    }
    __syncthreads();

    // phase B: warp-per-quad. q fixed per warp iteration -> no per-element
    // division. Lane L writes float2 elements {L, L+32, ..., L+128} of the
    // quad's 147-float2 row: each warp round = 256 contiguous bytes.
    {
        int warp = t >> 5, lane = t & 31;
        float2* ob2 = (float2*)(out + (size_t)q0 * 294);
        for (int q = warp; q < nq; q += 8) {
            const float* sq = sph_s + q * 49;
            const float* rq = rbf_s + q * RBF_ROW;
            float2* oq = ob2 + q * 147;
#pragma unroll
            for (int k = 0; k < 5; k++) {
                int r = lane + 32 * k;
                if (k < 4 || r < 147) {
                    int pk = tab_s[r];
                    float s = sq[pk >> 8];
                    float2 v = *(const float2*)(rq + (pk & 255));
                    __stcs(oq + r, make_float2(s * v.x, s * v.y));
                }
            }
        }
    }
}

extern "C" void kernel_launch(void* const* d_in, const int* in_sizes, int n_in,
                              void* d_out, int out_size) {
    const float* D   = (const float*)d_in[0];
    const float* Al  = (const float*)d_in[1];
    const float* Th  = (const float*)d_in[2];
    const int*   id4 = (const int*)d_in[3];
    float* out = (float*)d_out;
    int NQ = in_sizes[1];

    const KParams& H = host_consts();

    cudaFuncSetAttribute(fused_kernel, cudaFuncAttributeMaxDynamicSharedMemorySize, K_SMEM);

    fused_kernel<<<(NQ + QPB - 1) / QPB, TPB, K_SMEM>>>(D, Al, Th, id4, out, NQ, H);
}